// round 12
// baseline (speedup 1.0000x reference)
#include <cuda_runtime.h>
#include <cuda_bf16.h>
#include <cstdint>

// ============================================================================
// Problem constants
// ============================================================================
#define B_ROWS   4096
#define N2       8192
#define DIM      512
#define BETA_INV 12.5f
#define EPS_F    1e-8f
#define NTILE    64          // N2 / 128
#define NPAIRS   2080        // NTILE*(NTILE+1)/2 upper-triangular tiles

// ============================================================================
// Scratch (device globals — no allocation allowed)
// ============================================================================
__device__ __align__(128) __nv_bfloat16 g_xnb[(size_t)N2 * DIM]; // bf16 normalized rows, 8 MB
__device__ float g_d[B_ROWS];     // exact f32 diagonal cosine x1n.x2n
__device__ float g_bm[N2];        // bias margins (row means of bias_map)
__device__ float g_rowsum[N2];    // sum_{j!=i} exp(c_ij/beta)
__device__ float g_rtot[4];
__device__ float g_rcnt[4];

// ============================================================================
// Helpers
// ============================================================================
__device__ __forceinline__ uint32_t smem_to_u32(const void* p) {
    uint32_t a;
    asm("{ .reg .u64 t; cvta.to.shared.u64 t, %1; cvt.u32.u64 %0, t; }" : "=r"(a) : "l"(p));
    return a;
}

#define SMEM_SWIZZLE_128B(byte_offset) ((byte_offset) ^ (((byte_offset) >> 3) & 0x70))

__device__ __forceinline__ void cp_async16(uint32_t smem_dst, const void* gmem_src) {
    asm volatile("cp.async.cg.shared.global [%0], [%1], 16;"
                 :: "r"(smem_dst), "l"(gmem_src) : "memory");
}
#define CP_ASYNC_COMMIT() asm volatile("cp.async.commit_group;" ::: "memory")
#define CP_ASYNC_WAIT(n)  asm volatile("cp.async.wait_group %0;" :: "n"(n) : "memory")

__device__ __forceinline__ void ldmatrix_x4(uint32_t& r0, uint32_t& r1,
                                            uint32_t& r2, uint32_t& r3, uint32_t addr) {
    asm volatile("ldmatrix.sync.aligned.m8n8.x4.shared.b16 {%0,%1,%2,%3}, [%4];"
                 : "=r"(r0), "=r"(r1), "=r"(r2), "=r"(r3) : "r"(addr));
}

__device__ __forceinline__ void mma16816(float* c, const uint32_t* a,
                                         uint32_t b0, uint32_t b1) {
    asm volatile(
        "mma.sync.aligned.m16n8k16.row.col.f32.bf16.bf16.f32 "
        "{%0,%1,%2,%3}, {%4,%5,%6,%7}, {%8,%9}, {%0,%1,%2,%3};"
        : "+f"(c[0]), "+f"(c[1]), "+f"(c[2]), "+f"(c[3])
        : "r"(a[0]), "r"(a[1]), "r"(a[2]), "r"(a[3]), "r"(b0), "r"(b1));
}

// ============================================================================
// Kernel 1: prep — 2 row-pairs per warp, 128-thread blocks, 5 CTAs/SM.
// grid = 512 blocks x 128 threads; warp w of block b owns pairs
//   p0 = b*4+w (0..2047) and p1 = p0 + 2048.
// 16 independent float4 + 8 bias loads in flight per warp; 20 warps/SM.
// ============================================================================
__global__ void __launch_bounds__(128, 5) prep_fused_kernel(const float* __restrict__ x1,
                                                            const float* __restrict__ x2,
                                                            const float* __restrict__ bias_map,
                                                            const int* __restrict__ races) {
    const int tid = threadIdx.x;
    const int w = tid >> 5, l = tid & 31;
    const int p0 = blockIdx.x * 4 + w;           // 0..2047
    const int p1 = p0 + 2048;                    // 2048..4095

    __shared__ float st[4], sc[4];
    if (tid < 4) { st[tid] = 0.0f; sc[tid] = 0.0f; }
    // zero the 16 rowsum entries this block covers
    if (tid < 16) {
        int grp = tid >> 2, sub = tid & 3;
        int base = ((grp & 1) ? B_ROWS : 0) + ((grp >> 1) ? 2048 : 0);
        g_rowsum[base + blockIdx.x * 4 + sub] = 0.0f;
    }
    __syncthreads();      // st/sc initialized before warp atomics

    // ---- issue all independent loads up front (MLP = 16 + 8) ------------
    const float4* q10 = reinterpret_cast<const float4*>(x1 + (size_t)p0 * DIM) + l * 4;
    const float4* q20 = reinterpret_cast<const float4*>(x2 + (size_t)p0 * DIM) + l * 4;
    const float4* q11 = reinterpret_cast<const float4*>(x1 + (size_t)p1 * DIM) + l * 4;
    const float4* q21 = reinterpret_cast<const float4*>(x2 + (size_t)p1 * DIM) + l * 4;
    float4 a0[4], c0[4], a1[4], c1[4];
#pragma unroll
    for (int k = 0; k < 4; k++) a0[k] = q10[k];
#pragma unroll
    for (int k = 0; k < 4; k++) c0[k] = q20[k];
#pragma unroll
    for (int k = 0; k < 4; k++) a1[k] = q11[k];
#pragma unroll
    for (int k = 0; k < 4; k++) c1[k] = q21[k];

    const float* bmA = bias_map + (size_t)p0 * 64;
    const float* bmB = bias_map + (size_t)(B_ROWS + p0) * 64;
    const float* bmC = bias_map + (size_t)p1 * 64;
    const float* bmD = bias_map + (size_t)(B_ROWS + p1) * 64;
    float sbA = bmA[l] + bmA[32 + l];
    float sbB = bmB[l] + bmB[32 + l];
    float sbC = bmC[l] + bmC[32 + l];
    float sbD = bmD[l] + bmD[32 + l];

    // ---- reductions ------------------------------------------------------
    float n10 = 0.0f, n20 = 0.0f, dd0 = 0.0f;
    float n11 = 0.0f, n21 = 0.0f, dd1 = 0.0f;
#pragma unroll
    for (int k = 0; k < 4; k++) {
        n10 += a0[k].x * a0[k].x + a0[k].y * a0[k].y + a0[k].z * a0[k].z + a0[k].w * a0[k].w;
        n20 += c0[k].x * c0[k].x + c0[k].y * c0[k].y + c0[k].z * c0[k].z + c0[k].w * c0[k].w;
        dd0 += a0[k].x * c0[k].x + a0[k].y * c0[k].y + a0[k].z * c0[k].z + a0[k].w * c0[k].w;
        n11 += a1[k].x * a1[k].x + a1[k].y * a1[k].y + a1[k].z * a1[k].z + a1[k].w * a1[k].w;
        n21 += c1[k].x * c1[k].x + c1[k].y * c1[k].y + c1[k].z * c1[k].z + c1[k].w * c1[k].w;
        dd1 += a1[k].x * c1[k].x + a1[k].y * c1[k].y + a1[k].z * c1[k].z + a1[k].w * c1[k].w;
    }
#pragma unroll
    for (int o = 16; o > 0; o >>= 1) {
        n10 += __shfl_xor_sync(0xffffffffu, n10, o);
        n20 += __shfl_xor_sync(0xffffffffu, n20, o);
        dd0 += __shfl_xor_sync(0xffffffffu, dd0, o);
        n11 += __shfl_xor_sync(0xffffffffu, n11, o);
        n21 += __shfl_xor_sync(0xffffffffu, n21, o);
        dd1 += __shfl_xor_sync(0xffffffffu, dd1, o);
        sbA += __shfl_xor_sync(0xffffffffu, sbA, o);
        sbB += __shfl_xor_sync(0xffffffffu, sbB, o);
        sbC += __shfl_xor_sync(0xffffffffu, sbC, o);
        sbD += __shfl_xor_sync(0xffffffffu, sbD, o);
    }
    float i10 = 1.0f / fmaxf(sqrtf(n10), EPS_F);
    float i20 = 1.0f / fmaxf(sqrtf(n20), EPS_F);
    float i11 = 1.0f / fmaxf(sqrtf(n11), EPS_F);
    float i21 = 1.0f / fmaxf(sqrtf(n21), EPS_F);
    if (l == 0) {
        g_d[p0] = dd0 * i10 * i20;
        g_d[p1] = dd1 * i11 * i21;
        float mA = sbA * (1.0f / 64.0f), mB = sbB * (1.0f / 64.0f);
        float mC = sbC * (1.0f / 64.0f), mD = sbD * (1.0f / 64.0f);
        g_bm[p0] = mA;
        g_bm[B_ROWS + p0] = mB;
        g_bm[p1] = mC;
        g_bm[B_ROWS + p1] = mD;
        int r0 = races[p0], r1 = races[p1];
        atomicAdd(&st[r0], mA + mB);
        atomicAdd(&sc[r0], 2.0f);
        atomicAdd(&st[r1], mC + mD);
        atomicAdd(&sc[r1], 2.0f);
    }

    // ---- convert & store bf16 rows ---------------------------------------
    auto pack8 = [](float4 u, float4 v, float s) -> uint4 {
        __nv_bfloat162 h0 = __floats2bfloat162_rn(u.x * s, u.y * s);
        __nv_bfloat162 h1 = __floats2bfloat162_rn(u.z * s, u.w * s);
        __nv_bfloat162 h2 = __floats2bfloat162_rn(v.x * s, v.y * s);
        __nv_bfloat162 h3 = __floats2bfloat162_rn(v.z * s, v.w * s);
        uint4 r;
        r.x = *reinterpret_cast<uint32_t*>(&h0);
        r.y = *reinterpret_cast<uint32_t*>(&h1);
        r.z = *reinterpret_cast<uint32_t*>(&h2);
        r.w = *reinterpret_cast<uint32_t*>(&h3);
        return r;
    };
    uint4* o10 = reinterpret_cast<uint4*>(g_xnb + (size_t)p0 * DIM);
    uint4* o20 = reinterpret_cast<uint4*>(g_xnb + (size_t)(B_ROWS + p0) * DIM);
    uint4* o11 = reinterpret_cast<uint4*>(g_xnb + (size_t)p1 * DIM);
    uint4* o21 = reinterpret_cast<uint4*>(g_xnb + (size_t)(B_ROWS + p1) * DIM);
    o10[l * 2 + 0] = pack8(a0[0], a0[1], i10);
    o10[l * 2 + 1] = pack8(a0[2], a0[3], i10);
    o20[l * 2 + 0] = pack8(c0[0], c0[1], i20);
    o20[l * 2 + 1] = pack8(c0[2], c0[3], i20);
    o11[l * 2 + 0] = pack8(a1[0], a1[1], i11);
    o11[l * 2 + 1] = pack8(a1[2], a1[3], i11);
    o21[l * 2 + 0] = pack8(c1[0], c1[1], i21);
    o21[l * 2 + 1] = pack8(c1[2], c1[3], i21);

    __syncthreads();
    if (tid < 4) {
        atomicAdd(&g_rtot[tid], st[tid]);
        atomicAdd(&g_rcnt[tid], sc[tid]);
    }
}

// ============================================================================
// Kernel 2: SYMMETRIC bf16 mma.sync GEMM (best-measured R5/R10 variant).
// ============================================================================
#define CHUNK_BYTES 32768u                   // A(16K) + B(16K) per K=64 chunk
#define GEMM_SMEM_BYTES (3 * 32768 + 256)

__global__ void __launch_bounds__(256, 2) gemm_rowsum_sym_kernel() {
    extern __shared__ char smem_raw[];
    uint32_t TILES = (smem_to_u32(smem_raw) + 127u) & ~127u;

    // Map linear block id -> (tm, tn), tm <= tn (row-major upper triangle)
    int t = blockIdx.x;
    int tm = 0, rem = t;
    while (rem >= NTILE - tm) { rem -= NTILE - tm; tm++; }
    const int tn = tm + rem;
    const bool diag = (tm == tn);

    const int tid = threadIdx.x;
    const int wid = tid >> 5, lane = tid & 31;
    const int warp_m = wid & 3;        // 0..3 -> 32 rows each
    const int warp_n = wid >> 2;       // 0..1 -> 64 cols each
    const int group = lane >> 2;       // 0..7
    const int tq = lane & 3;           // 0..3

    // ---- Loop-invariant staging addresses -------------------------------
    const int r0c = tid >> 3;                       // rows tid>>3 + {0,32,64,96}
    const int c16 = tid & 7;
    const __nv_bfloat16* pa = g_xnb + (size_t)(tm * 128 + r0c) * DIM + c16 * 8;
    const __nv_bfloat16* pb = g_xnb + (size_t)(tn * 128 + r0c) * DIM + c16 * 8;
    uint32_t soff[4];
#pragma unroll
    for (int it = 0; it < 4; it++)
        soff[it] = SMEM_SWIZZLE_128B((uint32_t)((r0c + it * 32) * 128 + c16 * 16));

    auto stage = [&](int kc, uint32_t buf) {
        uint32_t abuf = TILES + buf * CHUNK_BYTES;
        uint32_t bbuf = abuf + 16384u;
        const __nv_bfloat16* ga = pa + kc * 64;
        const __nv_bfloat16* gb = pb + kc * 64;
#pragma unroll
        for (int it = 0; it < 4; it++)
            cp_async16(abuf + soff[it], ga + (size_t)(it * 32) * DIM);
#pragma unroll
        for (int it = 0; it < 4; it++)
            cp_async16(bbuf + soff[it], gb + (size_t)(it * 32) * DIM);
        CP_ASYNC_COMMIT();
    };

    float acc[2][8][4];
#pragma unroll
    for (int mf = 0; mf < 2; mf++)
#pragma unroll
        for (int nf = 0; nf < 8; nf++)
#pragma unroll
            for (int k = 0; k < 4; k++) acc[mf][nf][k] = 0.0f;

    stage(0, 0);
    stage(1, 1);

    // ---- Precomputed ldmatrix addressing --------------------------------
    const uint32_t sx = (uint32_t)((lane & 7) << 4);
    const uint32_t colg = (uint32_t)((lane >> 4) * 16);
    uint32_t co[4];
#pragma unroll
    for (int ks = 0; ks < 4; ks++) co[ks] = ((uint32_t)(ks * 32) + colg) ^ sx;
    const uint32_t rowA0 = (uint32_t)((warp_m * 32 + (lane & 15)) * 128);
    const uint32_t rowB0 = (uint32_t)((warp_n * 64 + (lane & 15)) * 128);

    uint32_t buf = 0;       // buffer holding chunk kc
    uint32_t bufn = 2;      // buffer for chunk kc+2

    for (int kc = 0; kc < 8; kc++) {
        if (kc == 7) { CP_ASYNC_WAIT(0); } else { CP_ASYNC_WAIT(1); }
        __syncthreads();
        if (kc < 6) stage(kc + 2, bufn);
        uint32_t abuf = TILES + buf * CHUNK_BYTES;
        uint32_t bbuf = abuf + 16384u;
        uint32_t aA0 = abuf + rowA0;
        uint32_t aA1 = aA0 + 16u * 128u;
        uint32_t bB0 = bbuf + rowB0;
        uint32_t bB1 = bB0 + 16u * 128u;
        uint32_t bB2 = bB1 + 16u * 128u;
        uint32_t bB3 = bB2 + 16u * 128u;
#pragma unroll
        for (int ks = 0; ks < 4; ks++) {
            uint32_t a[2][4];
            ldmatrix_x4(a[0][0], a[0][1], a[0][2], a[0][3], aA0 + co[ks]);
            ldmatrix_x4(a[1][0], a[1][1], a[1][2], a[1][3], aA1 + co[ks]);
            {
                uint32_t b0, b1, b2, b3;
                ldmatrix_x4(b0, b1, b2, b3, bB0 + co[ks]);
                mma16816(acc[0][0], a[0], b0, b2);
                mma16816(acc[0][1], a[0], b1, b3);
                mma16816(acc[1][0], a[1], b0, b2);
                mma16816(acc[1][1], a[1], b1, b3);
            }
            {
                uint32_t b0, b1, b2, b3;
                ldmatrix_x4(b0, b1, b2, b3, bB1 + co[ks]);
                mma16816(acc[0][2], a[0], b0, b2);
                mma16816(acc[0][3], a[0], b1, b3);
                mma16816(acc[1][2], a[1], b0, b2);
                mma16816(acc[1][3], a[1], b1, b3);
            }
            {
                uint32_t b0, b1, b2, b3;
                ldmatrix_x4(b0, b1, b2, b3, bB2 + co[ks]);
                mma16816(acc[0][4], a[0], b0, b2);
                mma16816(acc[0][5], a[0], b1, b3);
                mma16816(acc[1][4], a[1], b0, b2);
                mma16816(acc[1][5], a[1], b1, b3);
            }
            {
                uint32_t b0, b1, b2, b3;
                ldmatrix_x4(b0, b1, b2, b3, bB3 + co[ks]);
                mma16816(acc[0][6], a[0], b0, b2);
                mma16816(acc[0][7], a[0], b1, b3);
                mma16816(acc[1][6], a[1], b0, b2);
                mma16816(acc[1][7], a[1], b1, b3);
            }
        }
        buf = (buf == 2u) ? 0u : buf + 1u;
        bufn = (bufn == 2u) ? 0u : bufn + 1u;
    }

    // ------------------------------------------------------------------
    // Epilogue: exp(acc*12.5); rows -> rowsum[tm block]; off-diagonal
    // tiles also feed rowsum[tn block] via column sums (symmetry).
    // ------------------------------------------------------------------
    const int grow0 = tm * 128 + warp_m * 32 + group;
    const int gcol0 = tn * 128 + warp_n * 64 + tq * 2;

    float cs[8][2];
#pragma unroll
    for (int nf = 0; nf < 8; nf++) { cs[nf][0] = 0.0f; cs[nf][1] = 0.0f; }

#pragma unroll
    for (int mf = 0; mf < 2; mf++) {
        float s0 = 0.0f, s1 = 0.0f;
        int r0 = grow0 + mf * 16;
        int r1 = r0 + 8;
#pragma unroll
        for (int nf = 0; nf < 8; nf++) {
            int c0 = gcol0 + nf * 8;
            float e00 = __expf(acc[mf][nf][0] * BETA_INV);
            float e01 = __expf(acc[mf][nf][1] * BETA_INV);
            float e10 = __expf(acc[mf][nf][2] * BETA_INV);
            float e11 = __expf(acc[mf][nf][3] * BETA_INV);
            if (diag) {
                if (c0 == r0)     e00 = 0.0f;
                if (c0 + 1 == r0) e01 = 0.0f;
                if (c0 == r1)     e10 = 0.0f;
                if (c0 + 1 == r1) e11 = 0.0f;
            }
            s0 += e00 + e01;
            s1 += e10 + e11;
            cs[nf][0] += e00 + e10;
            cs[nf][1] += e01 + e11;
        }
        s0 += __shfl_xor_sync(0xffffffffu, s0, 1);
        s0 += __shfl_xor_sync(0xffffffffu, s0, 2);
        s1 += __shfl_xor_sync(0xffffffffu, s1, 1);
        s1 += __shfl_xor_sync(0xffffffffu, s1, 2);
        if (tq == 0) {
            atomicAdd(&g_rowsum[r0], s0);
            atomicAdd(&g_rowsum[r1], s1);
        }
    }

    if (!diag) {
#pragma unroll
        for (int nf = 0; nf < 8; nf++) {
#pragma unroll
            for (int p = 0; p < 2; p++) {
                float v = cs[nf][p];
                v += __shfl_xor_sync(0xffffffffu, v, 4);
                v += __shfl_xor_sync(0xffffffffu, v, 8);
                v += __shfl_xor_sync(0xffffffffu, v, 16);
                if (lane < 4) {
                    atomicAdd(&g_rowsum[gcol0 + nf * 8 + p], v);
                }
            }
        }
    }
}

// ============================================================================
// Kernel 3: final loss + margins (1024 threads); resets race accumulators.
// ============================================================================
__global__ void __launch_bounds__(1024) finalize_kernel(float* out, int out_size) {
    int tid = threadIdx.x;
    float acc = 0.0f;
#pragma unroll
    for (int k = 0; k < N2 / 1024; k++) {
        int i = tid + k * 1024;
        float dv = g_d[i & (B_ROWS - 1)];
        float bm = g_bm[i];
        float numlog = (dv - bm) * BETA_INV;
        float den = g_rowsum[i] - __expf(dv * BETA_INV) + __expf(numlog);
        acc += numlog - logf(den);
    }
#pragma unroll
    for (int o = 16; o > 0; o >>= 1) acc += __shfl_xor_sync(0xffffffffu, acc, o);
    __shared__ float sw[32];
    int w = tid >> 5, l = tid & 31;
    if (l == 0) sw[w] = acc;
    __syncthreads();
    if (tid == 0) {
        float tot = 0.0f;
#pragma unroll
        for (int k = 0; k < 32; k++) tot += sw[k];
        if (out_size > 0) out[0] = -tot / (float)N2;
    }
    if (tid >= 1 && tid < 5 && tid < out_size) {
        int r = tid - 1;
        float cnt = g_rcnt[r];
        out[tid] = (cnt > 0.0f) ? (g_rtot[r] / cnt) : 0.0f;
    }
    for (int k = 5 + tid; k < out_size; k += 1024) out[k] = 0.0f;
    __syncthreads();
    if (tid < 4) { g_rtot[tid] = 0.0f; g_rcnt[tid] = 0.0f; }
}

// ============================================================================
// Launch (3 kernels)
// ============================================================================
extern "C" void kernel_launch(void* const* d_in, const int* in_sizes, int n_in,
                              void* d_out, int out_size) {
    const float* x1       = (const float*)d_in[0];
    const float* x2       = (const float*)d_in[1];
    const int*   races    = (const int*)d_in[2];
    const float* bias_map = (const float*)d_in[3];
    float* out = (float*)d_out;

    cudaFuncSetAttribute(gemm_rowsum_sym_kernel,
                         cudaFuncAttributeMaxDynamicSharedMemorySize, GEMM_SMEM_BYTES);

    prep_fused_kernel<<<512, 128>>>(x1, x2, bias_map, races);
    gemm_rowsum_sym_kernel<<<NPAIRS, 256, GEMM_SMEM_BYTES>>>();
    finalize_kernel<<<1, 1024>>>(out, out_size);
}

// round 13
// speedup vs baseline: 1.0927x; 1.0927x over previous
#include <cuda_runtime.h>
#include <cuda_bf16.h>
#include <cstdint>

// ============================================================================
// Problem constants
// ============================================================================
#define B_ROWS   4096
#define N2       8192
#define DIM      512
#define BETA_INV 12.5f
#define EPS_F    1e-8f
#define NTILE    64          // N2 / 128
#define NPAIRS   2080        // NTILE*(NTILE+1)/2 upper-triangular tiles
#define NOFFDIAG 2016        // NTILE*(NTILE-1)/2 strictly-upper tiles

// ============================================================================
// Scratch (device globals — no allocation allowed)
// ============================================================================
__device__ __align__(128) __nv_bfloat16 g_xnb[(size_t)N2 * DIM]; // bf16 normalized rows, 8 MB
__device__ float g_d[B_ROWS];     // exact f32 diagonal cosine x1n.x2n
__device__ float g_bm[N2];        // bias margins (row means of bias_map)
__device__ float g_rowsum[N2];    // sum_{j!=i} exp(c_ij/beta)
__device__ float g_rtot[4];
__device__ float g_rcnt[4];

// ============================================================================
// Helpers
// ============================================================================
__device__ __forceinline__ uint32_t smem_to_u32(const void* p) {
    uint32_t a;
    asm("{ .reg .u64 t; cvta.to.shared.u64 t, %1; cvt.u32.u64 %0, t; }" : "=r"(a) : "l"(p));
    return a;
}

#define SMEM_SWIZZLE_128B(byte_offset) ((byte_offset) ^ (((byte_offset) >> 3) & 0x70))

__device__ __forceinline__ void cp_async16(uint32_t smem_dst, const void* gmem_src) {
    asm volatile("cp.async.cg.shared.global [%0], [%1], 16;"
                 :: "r"(smem_dst), "l"(gmem_src) : "memory");
}
#define CP_ASYNC_COMMIT() asm volatile("cp.async.commit_group;" ::: "memory")
#define CP_ASYNC_WAIT(n)  asm volatile("cp.async.wait_group %0;" :: "n"(n) : "memory")

__device__ __forceinline__ void ldmatrix_x4(uint32_t& r0, uint32_t& r1,
                                            uint32_t& r2, uint32_t& r3, uint32_t addr) {
    asm volatile("ldmatrix.sync.aligned.m8n8.x4.shared.b16 {%0,%1,%2,%3}, [%4];"
                 : "=r"(r0), "=r"(r1), "=r"(r2), "=r"(r3) : "r"(addr));
}

__device__ __forceinline__ void mma16816(float* c, const uint32_t* a,
                                         uint32_t b0, uint32_t b1) {
    asm volatile(
        "mma.sync.aligned.m16n8k16.row.col.f32.bf16.bf16.f32 "
        "{%0,%1,%2,%3}, {%4,%5,%6,%7}, {%8,%9}, {%0,%1,%2,%3};"
        : "+f"(c[0]), "+f"(c[1]), "+f"(c[2]), "+f"(c[3])
        : "r"(a[0]), "r"(a[1]), "r"(a[2]), "r"(a[3]), "r"(b0), "r"(b1));
}

// ============================================================================
// Kernel 1: prep (R10 best-measured: 1 pair/warp, 1024 x 128, 56 regs)
// ============================================================================
__global__ void __launch_bounds__(128) prep_fused_kernel(const float* __restrict__ x1,
                                                         const float* __restrict__ x2,
                                                         const float* __restrict__ bias_map,
                                                         const int* __restrict__ races) {
    const int tid = threadIdx.x;
    const int w = tid >> 5, l = tid & 31;
    const int i = blockIdx.x * 4 + w;            // row pair 0..4095

    __shared__ float st[4], sc[4];
    if (tid < 4) { st[tid] = 0.0f; sc[tid] = 0.0f; }
    if (tid < 4) g_rowsum[blockIdx.x * 4 + tid] = 0.0f;
    else if (tid < 8) g_rowsum[B_ROWS + blockIdx.x * 4 + (tid - 4)] = 0.0f;
    __syncthreads();

    const float4* p1 = reinterpret_cast<const float4*>(x1 + (size_t)i * DIM);
    const float4* p2 = reinterpret_cast<const float4*>(x2 + (size_t)i * DIM);
    float4 a[4], c[4];
#pragma unroll
    for (int k = 0; k < 4; k++) a[k] = p1[l * 4 + k];
#pragma unroll
    for (int k = 0; k < 4; k++) c[k] = p2[l * 4 + k];

    const float* bm1 = bias_map + (size_t)i * 64;
    const float* bm2 = bias_map + (size_t)(B_ROWS + i) * 64;
    float sb1 = bm1[l] + bm1[32 + l];
    float sb2 = bm2[l] + bm2[32 + l];

    float n1 = 0.0f, n2 = 0.0f, dd = 0.0f;
#pragma unroll
    for (int k = 0; k < 4; k++) {
        n1 += a[k].x * a[k].x + a[k].y * a[k].y + a[k].z * a[k].z + a[k].w * a[k].w;
        n2 += c[k].x * c[k].x + c[k].y * c[k].y + c[k].z * c[k].z + c[k].w * c[k].w;
        dd += a[k].x * c[k].x + a[k].y * c[k].y + a[k].z * c[k].z + a[k].w * c[k].w;
    }
#pragma unroll
    for (int o = 16; o > 0; o >>= 1) {
        n1 += __shfl_xor_sync(0xffffffffu, n1, o);
        n2 += __shfl_xor_sync(0xffffffffu, n2, o);
        dd += __shfl_xor_sync(0xffffffffu, dd, o);
        sb1 += __shfl_xor_sync(0xffffffffu, sb1, o);
        sb2 += __shfl_xor_sync(0xffffffffu, sb2, o);
    }
    float m1 = fmaxf(sqrtf(n1), EPS_F);
    float m2 = fmaxf(sqrtf(n2), EPS_F);
    float i1 = 1.0f / m1, i2 = 1.0f / m2;
    if (l == 0) {
        g_d[i] = dd * i1 * i2;
        float mean1 = sb1 * (1.0f / 64.0f);
        float mean2 = sb2 * (1.0f / 64.0f);
        g_bm[i] = mean1;
        g_bm[B_ROWS + i] = mean2;
        int rc = races[i];
        atomicAdd(&st[rc], mean1 + mean2);
        atomicAdd(&sc[rc], 2.0f);
    }

    auto pack8 = [](float4 u, float4 v, float s) -> uint4 {
        __nv_bfloat162 h0 = __floats2bfloat162_rn(u.x * s, u.y * s);
        __nv_bfloat162 h1 = __floats2bfloat162_rn(u.z * s, u.w * s);
        __nv_bfloat162 h2 = __floats2bfloat162_rn(v.x * s, v.y * s);
        __nv_bfloat162 h3 = __floats2bfloat162_rn(v.z * s, v.w * s);
        uint4 r;
        r.x = *reinterpret_cast<uint32_t*>(&h0);
        r.y = *reinterpret_cast<uint32_t*>(&h1);
        r.z = *reinterpret_cast<uint32_t*>(&h2);
        r.w = *reinterpret_cast<uint32_t*>(&h3);
        return r;
    };
    uint4* o1 = reinterpret_cast<uint4*>(g_xnb + (size_t)i * DIM);
    uint4* o2 = reinterpret_cast<uint4*>(g_xnb + (size_t)(B_ROWS + i) * DIM);
    o1[l * 2 + 0] = pack8(a[0], a[1], i1);
    o1[l * 2 + 1] = pack8(a[2], a[3], i1);
    o2[l * 2 + 0] = pack8(c[0], c[1], i2);
    o2[l * 2 + 1] = pack8(c[2], c[3], i2);

    __syncthreads();
    if (tid < 4) {
        atomicAdd(&g_rtot[tid], st[tid]);
        atomicAdd(&g_rcnt[tid], sc[tid]);
    }
}

// ============================================================================
// Kernel 2: SYMMETRIC bf16 mma.sync GEMM (best-measured R5/R10 variant).
// Block-id remap: strictly-upper tiles first (blocks 0..2015), diagonal
// tiles last (2016..2079) so the wave-quantization tail runs the cheapest
// (diag) epilogues.
// ============================================================================
#define CHUNK_BYTES 32768u                   // A(16K) + B(16K) per K=64 chunk
#define GEMM_SMEM_BYTES (3 * 32768 + 256)

__global__ void __launch_bounds__(256, 2) gemm_rowsum_sym_kernel() {
    extern __shared__ char smem_raw[];
    uint32_t TILES = (smem_to_u32(smem_raw) + 127u) & ~127u;

    // Map linear block id -> (tm, tn): off-diagonal (tm < tn) first, then diag.
    int t = blockIdx.x;
    int tm, tn;
    if (t >= NOFFDIAG) {
        tm = t - NOFFDIAG;
        tn = tm;
    } else {
        tm = 0;
        int rem = t;
        while (rem >= NTILE - 1 - tm) { rem -= NTILE - 1 - tm; tm++; }
        tn = tm + 1 + rem;
    }
    const bool diag = (tm == tn);

    const int tid = threadIdx.x;
    const int wid = tid >> 5, lane = tid & 31;
    const int warp_m = wid & 3;        // 0..3 -> 32 rows each
    const int warp_n = wid >> 2;       // 0..1 -> 64 cols each
    const int group = lane >> 2;       // 0..7
    const int tq = lane & 3;           // 0..3

    // ---- Loop-invariant staging addresses -------------------------------
    const int r0c = tid >> 3;                       // rows tid>>3 + {0,32,64,96}
    const int c16 = tid & 7;
    const __nv_bfloat16* pa = g_xnb + (size_t)(tm * 128 + r0c) * DIM + c16 * 8;
    const __nv_bfloat16* pb = g_xnb + (size_t)(tn * 128 + r0c) * DIM + c16 * 8;
    uint32_t soff[4];
#pragma unroll
    for (int it = 0; it < 4; it++)
        soff[it] = SMEM_SWIZZLE_128B((uint32_t)((r0c + it * 32) * 128 + c16 * 16));

    auto stage = [&](int kc, uint32_t buf) {
        uint32_t abuf = TILES + buf * CHUNK_BYTES;
        uint32_t bbuf = abuf + 16384u;
        const __nv_bfloat16* ga = pa + kc * 64;
        const __nv_bfloat16* gb = pb + kc * 64;
#pragma unroll
        for (int it = 0; it < 4; it++)
            cp_async16(abuf + soff[it], ga + (size_t)(it * 32) * DIM);
#pragma unroll
        for (int it = 0; it < 4; it++)
            cp_async16(bbuf + soff[it], gb + (size_t)(it * 32) * DIM);
        CP_ASYNC_COMMIT();
    };

    float acc[2][8][4];
#pragma unroll
    for (int mf = 0; mf < 2; mf++)
#pragma unroll
        for (int nf = 0; nf < 8; nf++)
#pragma unroll
            for (int k = 0; k < 4; k++) acc[mf][nf][k] = 0.0f;

    stage(0, 0);
    stage(1, 1);

    // ---- Precomputed ldmatrix addressing --------------------------------
    const uint32_t sx = (uint32_t)((lane & 7) << 4);
    const uint32_t colg = (uint32_t)((lane >> 4) * 16);
    uint32_t co[4];
#pragma unroll
    for (int ks = 0; ks < 4; ks++) co[ks] = ((uint32_t)(ks * 32) + colg) ^ sx;
    const uint32_t rowA0 = (uint32_t)((warp_m * 32 + (lane & 15)) * 128);
    const uint32_t rowB0 = (uint32_t)((warp_n * 64 + (lane & 15)) * 128);

    uint32_t buf = 0;       // buffer holding chunk kc
    uint32_t bufn = 2;      // buffer for chunk kc+2

    for (int kc = 0; kc < 8; kc++) {
        if (kc == 7) { CP_ASYNC_WAIT(0); } else { CP_ASYNC_WAIT(1); }
        __syncthreads();
        if (kc < 6) stage(kc + 2, bufn);
        uint32_t abuf = TILES + buf * CHUNK_BYTES;
        uint32_t bbuf = abuf + 16384u;
        uint32_t aA0 = abuf + rowA0;
        uint32_t aA1 = aA0 + 16u * 128u;
        uint32_t bB0 = bbuf + rowB0;
        uint32_t bB1 = bB0 + 16u * 128u;
        uint32_t bB2 = bB1 + 16u * 128u;
        uint32_t bB3 = bB2 + 16u * 128u;
#pragma unroll
        for (int ks = 0; ks < 4; ks++) {
            uint32_t a[2][4];
            ldmatrix_x4(a[0][0], a[0][1], a[0][2], a[0][3], aA0 + co[ks]);
            ldmatrix_x4(a[1][0], a[1][1], a[1][2], a[1][3], aA1 + co[ks]);
            {
                uint32_t b0, b1, b2, b3;
                ldmatrix_x4(b0, b1, b2, b3, bB0 + co[ks]);
                mma16816(acc[0][0], a[0], b0, b2);
                mma16816(acc[0][1], a[0], b1, b3);
                mma16816(acc[1][0], a[1], b0, b2);
                mma16816(acc[1][1], a[1], b1, b3);
            }
            {
                uint32_t b0, b1, b2, b3;
                ldmatrix_x4(b0, b1, b2, b3, bB1 + co[ks]);
                mma16816(acc[0][2], a[0], b0, b2);
                mma16816(acc[0][3], a[0], b1, b3);
                mma16816(acc[1][2], a[1], b0, b2);
                mma16816(acc[1][3], a[1], b1, b3);
            }
            {
                uint32_t b0, b1, b2, b3;
                ldmatrix_x4(b0, b1, b2, b3, bB2 + co[ks]);
                mma16816(acc[0][4], a[0], b0, b2);
                mma16816(acc[0][5], a[0], b1, b3);
                mma16816(acc[1][4], a[1], b0, b2);
                mma16816(acc[1][5], a[1], b1, b3);
            }
            {
                uint32_t b0, b1, b2, b3;
                ldmatrix_x4(b0, b1, b2, b3, bB3 + co[ks]);
                mma16816(acc[0][6], a[0], b0, b2);
                mma16816(acc[0][7], a[0], b1, b3);
                mma16816(acc[1][6], a[1], b0, b2);
                mma16816(acc[1][7], a[1], b1, b3);
            }
        }
        buf = (buf == 2u) ? 0u : buf + 1u;
        bufn = (bufn == 2u) ? 0u : bufn + 1u;
    }

    // ------------------------------------------------------------------
    // Epilogue: exp(acc*12.5); rows -> rowsum[tm block]; off-diagonal
    // tiles also feed rowsum[tn block] via column sums (symmetry).
    // ------------------------------------------------------------------
    const int grow0 = tm * 128 + warp_m * 32 + group;
    const int gcol0 = tn * 128 + warp_n * 64 + tq * 2;

    float cs[8][2];
#pragma unroll
    for (int nf = 0; nf < 8; nf++) { cs[nf][0] = 0.0f; cs[nf][1] = 0.0f; }

#pragma unroll
    for (int mf = 0; mf < 2; mf++) {
        float s0 = 0.0f, s1 = 0.0f;
        int r0 = grow0 + mf * 16;
        int r1 = r0 + 8;
#pragma unroll
        for (int nf = 0; nf < 8; nf++) {
            int c0 = gcol0 + nf * 8;
            float e00 = __expf(acc[mf][nf][0] * BETA_INV);
            float e01 = __expf(acc[mf][nf][1] * BETA_INV);
            float e10 = __expf(acc[mf][nf][2] * BETA_INV);
            float e11 = __expf(acc[mf][nf][3] * BETA_INV);
            if (diag) {
                if (c0 == r0)     e00 = 0.0f;
                if (c0 + 1 == r0) e01 = 0.0f;
                if (c0 == r1)     e10 = 0.0f;
                if (c0 + 1 == r1) e11 = 0.0f;
            }
            s0 += e00 + e01;
            s1 += e10 + e11;
            cs[nf][0] += e00 + e10;
            cs[nf][1] += e01 + e11;
        }
        s0 += __shfl_xor_sync(0xffffffffu, s0, 1);
        s0 += __shfl_xor_sync(0xffffffffu, s0, 2);
        s1 += __shfl_xor_sync(0xffffffffu, s1, 1);
        s1 += __shfl_xor_sync(0xffffffffu, s1, 2);
        if (tq == 0) {
            atomicAdd(&g_rowsum[r0], s0);
            atomicAdd(&g_rowsum[r1], s1);
        }
    }

    if (!diag) {
#pragma unroll
        for (int nf = 0; nf < 8; nf++) {
#pragma unroll
            for (int p = 0; p < 2; p++) {
                float v = cs[nf][p];
                v += __shfl_xor_sync(0xffffffffu, v, 4);
                v += __shfl_xor_sync(0xffffffffu, v, 8);
                v += __shfl_xor_sync(0xffffffffu, v, 16);
                if (lane < 4) {
                    atomicAdd(&g_rowsum[gcol0 + nf * 8 + p], v);
                }
            }
        }
    }
}

// ============================================================================
// Kernel 3: final loss + margins (1024 threads); resets race accumulators.
// ============================================================================
__global__ void __launch_bounds__(1024) finalize_kernel(float* out, int out_size) {
    int tid = threadIdx.x;
    float acc = 0.0f;
#pragma unroll
    for (int k = 0; k < N2 / 1024; k++) {
        int i = tid + k * 1024;
        float dv = g_d[i & (B_ROWS - 1)];
        float bm = g_bm[i];
        float numlog = (dv - bm) * BETA_INV;
        float den = g_rowsum[i] - __expf(dv * BETA_INV) + __expf(numlog);
        acc += numlog - logf(den);
    }
#pragma unroll
    for (int o = 16; o > 0; o >>= 1) acc += __shfl_xor_sync(0xffffffffu, acc, o);
    __shared__ float sw[32];
    int w = tid >> 5, l = tid & 31;
    if (l == 0) sw[w] = acc;
    __syncthreads();
    if (tid == 0) {
        float tot = 0.0f;
#pragma unroll
        for (int k = 0; k < 32; k++) tot += sw[k];
        if (out_size > 0) out[0] = -tot / (float)N2;
    }
    if (tid >= 1 && tid < 5 && tid < out_size) {
        int r = tid - 1;
        float cnt = g_rcnt[r];
        out[tid] = (cnt > 0.0f) ? (g_rtot[r] / cnt) : 0.0f;
    }
    for (int k = 5 + tid; k < out_size; k += 1024) out[k] = 0.0f;
    __syncthreads();
    if (tid < 4) { g_rtot[tid] = 0.0f; g_rcnt[tid] = 0.0f; }
}

// ============================================================================
// Launch (3 kernels)
// ============================================================================
extern "C" void kernel_launch(void* const* d_in, const int* in_sizes, int n_in,
                              void* d_out, int out_size) {
    const float* x1       = (const float*)d_in[0];
    const float* x2       = (const float*)d_in[1];
    const int*   races    = (const int*)d_in[2];
    const float* bias_map = (const float*)d_in[3];
    float* out = (float*)d_out;

    cudaFuncSetAttribute(gemm_rowsum_sym_kernel,
                         cudaFuncAttributeMaxDynamicSharedMemorySize, GEMM_SMEM_BYTES);

    prep_fused_kernel<<<1024, 128>>>(x1, x2, bias_map, races);
    gemm_rowsum_sym_kernel<<<NPAIRS, 256, GEMM_SMEM_BYTES>>>();
    finalize_kernel<<<1, 1024>>>(out, out_size);
}